// round 2
// baseline (speedup 1.0000x reference)
#include <cuda_runtime.h>
#include <cstdint>

// ---------------------------------------------------------------------------
// SingleAttention: out = softmax((query Wq^T + bq)(key Wk^T + bk)^T / 32) value
// B=4, S=2048, D=1024.  TF32 mma.sync GEMMs, fp32 accumulate + fp32 softmax.
// ---------------------------------------------------------------------------

// Scratch (static device globals: allocation-guard safe)
__device__ float g_Q[4ll * 2048 * 1024];
__device__ float g_K[4ll * 2048 * 1024];
__device__ float g_P[4ll * 2048 * 2048];

__device__ __forceinline__ uint32_t f2tf32(float x) {
    uint32_t r;
    asm("cvt.rna.tf32.f32 %0, %1;" : "=r"(r) : "f"(x));
    return r;
}

__device__ __forceinline__ void mma_m16n8k8(float c[4], const uint32_t a[4], const uint32_t b[2]) {
    asm volatile(
        "mma.sync.aligned.m16n8k8.row.col.f32.tf32.tf32.f32 "
        "{%0,%1,%2,%3}, {%4,%5,%6,%7}, {%8,%9}, {%0,%1,%2,%3};\n"
        : "+f"(c[0]), "+f"(c[1]), "+f"(c[2]), "+f"(c[3])
        : "r"(a[0]), "r"(a[1]), "r"(a[2]), "r"(a[3]), "r"(b[0]), "r"(b[1]));
}

// C[M,N] = alpha * A[M,K] * op(B) + bias
//   TRANSB=true : B is [N,K] row-major (C = A * B^T)
//   TRANSB=false: B is [K,N] row-major (C = A * B)
// All of M, N divisible by 128; K divisible by 32. lda=K, ldc=N.
template <bool TRANSB>
__global__ __launch_bounds__(256) void gemm_tf32(
    const float* __restrict__ A, const float* __restrict__ B, float* __restrict__ C,
    int M, int N, int K,
    long long aBatch, long long bBatch, long long cBatch,
    const float* __restrict__ bias, float alpha)
{
    constexpr int BM = 128, BN = 128, BK = 32;
    constexpr int AP  = 40;   // padded row stride (floats) for As / BsT: conflict-free frag loads
    constexpr int BNP = 136;  // padded row stride for BsN (NN path)

    __shared__ __align__(16) uint32_t As[BM * AP];
    __shared__ __align__(16) uint32_t Bs[BM * AP];  // NN path uses [BK][BNP] = 4352 <= 5120

    const int tid  = threadIdx.x;
    const int warp = tid >> 5, lane = tid & 31;
    const int gid  = lane >> 2, tg = lane & 3;
    const int wr   = (warp & 3) * 32;   // warp row in block tile
    const int wc   = (warp >> 2) * 64;  // warp col in block tile

    const int bm = blockIdx.y * BM;
    const int bn = blockIdx.x * BN;
    const int bz = blockIdx.z;

    const float* Ag = A + (long long)bz * aBatch + (long long)bm * K;
    const float* Bg = B + (long long)bz * bBatch;
    float*       Cg = C + (long long)bz * cBatch + (long long)bm * N + bn;

    float acc[2][8][4];
#pragma unroll
    for (int i = 0; i < 2; i++)
#pragma unroll
        for (int j = 0; j < 8; j++)
#pragma unroll
            for (int q = 0; q < 4; q++) acc[i][j][q] = 0.f;

    for (int kt = 0; kt < K; kt += BK) {
        // ---- load A tile 128x32 (float4) ----
#pragma unroll
        for (int it = 0; it < 4; it++) {
            int i = tid + it * 256;
            int r = i >> 3, c = (i & 7) << 2;
            float4 v = *reinterpret_cast<const float4*>(Ag + (long long)r * K + kt + c);
            uint32_t* dst = &As[r * AP + c];
            dst[0] = f2tf32(v.x); dst[1] = f2tf32(v.y);
            dst[2] = f2tf32(v.z); dst[3] = f2tf32(v.w);
        }
        // ---- load B tile ----
        if (TRANSB) {
#pragma unroll
            for (int it = 0; it < 4; it++) {
                int i = tid + it * 256;
                int r = i >> 3, c = (i & 7) << 2;
                float4 v = *reinterpret_cast<const float4*>(Bg + (long long)(bn + r) * K + kt + c);
                uint32_t* dst = &Bs[r * AP + c];
                dst[0] = f2tf32(v.x); dst[1] = f2tf32(v.y);
                dst[2] = f2tf32(v.z); dst[3] = f2tf32(v.w);
            }
        } else {
#pragma unroll
            for (int it = 0; it < 4; it++) {
                int i = tid + it * 256;
                int k = i >> 5, n = (i & 31) << 2;
                float4 v = *reinterpret_cast<const float4*>(Bg + (long long)(kt + k) * N + bn + n);
                uint32_t* dst = &Bs[k * BNP + n];
                dst[0] = f2tf32(v.x); dst[1] = f2tf32(v.y);
                dst[2] = f2tf32(v.z); dst[3] = f2tf32(v.w);
            }
        }
        __syncthreads();

        // ---- compute: 4 k-steps of 8 ----
#pragma unroll
        for (int ks = 0; ks < 4; ks++) {
            const int kk = ks * 8;
            uint32_t af[2][4];
#pragma unroll
            for (int mi = 0; mi < 2; mi++) {
                const int r = wr + mi * 16;
                af[mi][0] = As[(r + gid    ) * AP + kk + tg    ];
                af[mi][1] = As[(r + gid + 8) * AP + kk + tg    ];
                af[mi][2] = As[(r + gid    ) * AP + kk + tg + 4];
                af[mi][3] = As[(r + gid + 8) * AP + kk + tg + 4];
            }
#pragma unroll
            for (int ni = 0; ni < 8; ni++) {
                const int c = wc + ni * 8;
                uint32_t bf[2];
                if (TRANSB) {
                    bf[0] = Bs[(c + gid) * AP + kk + tg    ];
                    bf[1] = Bs[(c + gid) * AP + kk + tg + 4];
                } else {
                    bf[0] = Bs[(kk + tg    ) * BNP + c + gid];
                    bf[1] = Bs[(kk + tg + 4) * BNP + c + gid];
                }
                mma_m16n8k8(acc[0][ni], af[0], bf);
                mma_m16n8k8(acc[1][ni], af[1], bf);
            }
        }
        __syncthreads();
    }

    // ---- epilogue: alpha + bias, float2 stores ----
#pragma unroll
    for (int mi = 0; mi < 2; mi++) {
#pragma unroll
        for (int ni = 0; ni < 8; ni++) {
            const int r = wr + mi * 16 + gid;
            const int c = wc + ni * 8 + tg * 2;
            float b0 = bias ? bias[bn + c]     : 0.f;
            float b1 = bias ? bias[bn + c + 1] : 0.f;
            float2 v0 = make_float2(acc[mi][ni][0] * alpha + b0, acc[mi][ni][1] * alpha + b1);
            float2 v1 = make_float2(acc[mi][ni][2] * alpha + b0, acc[mi][ni][3] * alpha + b1);
            *reinterpret_cast<float2*>(Cg + (long long)r * N + c)       = v0;
            *reinterpret_cast<float2*>(Cg + (long long)(r + 8) * N + c) = v1;
        }
    }
}

// In-place softmax over rows of length 2048. One CTA (256 thr) per row;
// row held in registers: single global load + single store.
__global__ __launch_bounds__(256) void softmax2048(float* __restrict__ P) {
    constexpr int S = 2048;
    float* p = P + (long long)blockIdx.x * S;
    const int tid = threadIdx.x;

    float v[8];
    float mx = -3.4e38f;
#pragma unroll
    for (int j = 0; j < 8; j++) { v[j] = p[tid + j * 256]; mx = fmaxf(mx, v[j]); }
#pragma unroll
    for (int o = 16; o; o >>= 1) mx = fmaxf(mx, __shfl_xor_sync(0xffffffffu, mx, o));

    __shared__ float redm[8], reds[8];
    if ((tid & 31) == 0) redm[tid >> 5] = mx;
    __syncthreads();
    mx = redm[0];
#pragma unroll
    for (int j = 1; j < 8; j++) mx = fmaxf(mx, redm[j]);

    float s = 0.f;
#pragma unroll
    for (int j = 0; j < 8; j++) { v[j] = __expf(v[j] - mx); s += v[j]; }
#pragma unroll
    for (int o = 16; o; o >>= 1) s += __shfl_xor_sync(0xffffffffu, s, o);
    if ((tid & 31) == 0) reds[tid >> 5] = s;
    __syncthreads();
    s = reds[0];
#pragma unroll
    for (int j = 1; j < 8; j++) s += reds[j];

    const float inv = 1.0f / s;
#pragma unroll
    for (int j = 0; j < 8; j++) p[tid + j * 256] = v[j] * inv;
}

extern "C" void kernel_launch(void* const* d_in, const int* in_sizes, int n_in,
                              void* d_out, int out_size)
{
    const float* query  = (const float*)d_in[0];
    const float* key_in = (const float*)d_in[1];
    const float* value  = (const float*)d_in[2];
    const float* Wq     = (const float*)d_in[3];
    const float* bq     = (const float*)d_in[4];
    const float* Wk     = (const float*)d_in[5];
    const float* bk     = (const float*)d_in[6];
    // d_in[7] (Wv), d_in[8] (bv): unused by the reference math.
    float* out = (float*)d_out;

    float *Q, *Kb, *P;
    cudaGetSymbolAddress((void**)&Q,  g_Q);
    cudaGetSymbolAddress((void**)&Kb, g_K);
    cudaGetSymbolAddress((void**)&P,  g_P);

    constexpr int B = 4, S = 2048, D = 1024;
    const long long SD = (long long)S * D;
    const long long SS = (long long)S * S;
    const float scale = 0.03125f;  // 1/sqrt(1024)

    // Q = query @ Wq^T + bq ; K = key_in @ Wk^T + bk
    gemm_tf32<true><<<dim3(D / 128, S / 128, B), 256>>>(query,  Wq, Q,  S, D, D, SD, 0, SD, bq, 1.f);
    gemm_tf32<true><<<dim3(D / 128, S / 128, B), 256>>>(key_in, Wk, Kb, S, D, D, SD, 0, SD, bk, 1.f);
    // P = (Q @ K^T) * scale
    gemm_tf32<true><<<dim3(S / 128, S / 128, B), 256>>>(Q, Kb, P, S, S, D, SD, SD, SS, nullptr, scale);
    // softmax rows in place
    softmax2048<<<B * S, 256>>>(P);
    // out = P @ value   (NN)
    gemm_tf32<false><<<dim3(D / 128, S / 128, B), 256>>>(P, value, out, S, D, S, SS, SD, SD, nullptr, 1.f);
}

// round 7
// speedup vs baseline: 1.0024x; 1.0024x over previous
#include <cuda_runtime.h>
#include <cstdint>

// ---------------------------------------------------------------------------
// SingleAttention: out = softmax((query Wq^T + bq)(key Wk^T + bk)^T / 32) value
// B=4, S=2048, D=1024.  TF32 mma.sync GEMMs, fp32 accumulate + fp32 softmax.
// ---------------------------------------------------------------------------

// Scratch (static device globals: allocation-guard safe)
__device__ float g_Q[4ll * 2048 * 1024];
__device__ float g_K[4ll * 2048 * 1024];
__device__ float g_P[4ll * 2048 * 2048];

__device__ __forceinline__ uint32_t f2tf32(float x) {
    uint32_t r;
    asm("cvt.rna.tf32.f32 %0, %1;" : "=r"(r) : "f"(x));
    return r;
}

__device__ __forceinline__ void mma_m16n8k8(float c[4], const uint32_t a[4], const uint32_t b[2]) {
    asm volatile(
        "mma.sync.aligned.m16n8k8.row.col.f32.tf32.tf32.f32 "
        "{%0,%1,%2,%3}, {%4,%5,%6,%7}, {%8,%9}, {%0,%1,%2,%3};\n"
        : "+f"(c[0]), "+f"(c[1]), "+f"(c[2]), "+f"(c[3])
        : "r"(a[0]), "r"(a[1]), "r"(a[2]), "r"(a[3]), "r"(b[0]), "r"(b[1]));
}

// C[M,N] = alpha * A[M,K] * op(B) + bias
//   TRANSB=true : B is [N,K] row-major (C = A * B^T)
//   TRANSB=false: B is [K,N] row-major (C = A * B)
// All of M, N divisible by 128; K divisible by 32. lda=K, ldc=N.
template <bool TRANSB>
__global__ __launch_bounds__(256) void gemm_tf32(
    const float* __restrict__ A, const float* __restrict__ B, float* __restrict__ C,
    int M, int N, int K,
    long long aBatch, long long bBatch, long long cBatch,
    const float* __restrict__ bias, float alpha)
{
    constexpr int BM = 128, BN = 128, BK = 32;
    constexpr int AP  = 40;   // padded row stride (floats) for As / BsT: conflict-free frag loads
    constexpr int BNP = 136;  // padded row stride for BsN (NN path)

    __shared__ __align__(16) uint32_t As[BM * AP];
    __shared__ __align__(16) uint32_t Bs[BM * AP];  // NN path uses [BK][BNP] = 4352 <= 5120

    const int tid  = threadIdx.x;
    const int warp = tid >> 5, lane = tid & 31;
    const int gid  = lane >> 2, tg = lane & 3;
    const int wr   = (warp & 3) * 32;   // warp row in block tile
    const int wc   = (warp >> 2) * 64;  // warp col in block tile

    const int bm = blockIdx.y * BM;
    const int bn = blockIdx.x * BN;
    const int bz = blockIdx.z;

    const float* Ag = A + (long long)bz * aBatch + (long long)bm * K;
    const float* Bg = B + (long long)bz * bBatch;
    float*       Cg = C + (long long)bz * cBatch + (long long)bm * N + bn;

    float acc[2][8][4];
#pragma unroll
    for (int i = 0; i < 2; i++)
#pragma unroll
        for (int j = 0; j < 8; j++)
#pragma unroll
            for (int q = 0; q < 4; q++) acc[i][j][q] = 0.f;

    for (int kt = 0; kt < K; kt += BK) {
        // ---- load A tile 128x32 (float4) ----
#pragma unroll
        for (int it = 0; it < 4; it++) {
            int i = tid + it * 256;
            int r = i >> 3, c = (i & 7) << 2;
            float4 v = *reinterpret_cast<const float4*>(Ag + (long long)r * K + kt + c);
            uint32_t* dst = &As[r * AP + c];
            dst[0] = f2tf32(v.x); dst[1] = f2tf32(v.y);
            dst[2] = f2tf32(v.z); dst[3] = f2tf32(v.w);
        }
        // ---- load B tile ----
        if (TRANSB) {
#pragma unroll
            for (int it = 0; it < 4; it++) {
                int i = tid + it * 256;
                int r = i >> 3, c = (i & 7) << 2;
                float4 v = *reinterpret_cast<const float4*>(Bg + (long long)(bn + r) * K + kt + c);
                uint32_t* dst = &Bs[r * AP + c];
                dst[0] = f2tf32(v.x); dst[1] = f2tf32(v.y);
                dst[2] = f2tf32(v.z); dst[3] = f2tf32(v.w);
            }
        } else {
#pragma unroll
            for (int it = 0; it < 4; it++) {
                int i = tid + it * 256;
                int k = i >> 5, n = (i & 31) << 2;
                float4 v = *reinterpret_cast<const float4*>(Bg + (long long)(kt + k) * N + bn + n);
                uint32_t* dst = &Bs[k * BNP + n];
                dst[0] = f2tf32(v.x); dst[1] = f2tf32(v.y);
                dst[2] = f2tf32(v.z); dst[3] = f2tf32(v.w);
            }
        }
        __syncthreads();

        // ---- compute: 4 k-steps of 8 ----
#pragma unroll
        for (int ks = 0; ks < 4; ks++) {
            const int kk = ks * 8;
            uint32_t af[2][4];
#pragma unroll
            for (int mi = 0; mi < 2; mi++) {
                const int r = wr + mi * 16;
                af[mi][0] = As[(r + gid    ) * AP + kk + tg    ];
                af[mi][1] = As[(r + gid + 8) * AP + kk + tg    ];
                af[mi][2] = As[(r + gid    ) * AP + kk + tg + 4];
                af[mi][3] = As[(r + gid + 8) * AP + kk + tg + 4];
            }
#pragma unroll
            for (int ni = 0; ni < 8; ni++) {
                const int c = wc + ni * 8;
                uint32_t bf[2];
                if (TRANSB) {
                    bf[0] = Bs[(c + gid) * AP + kk + tg    ];
                    bf[1] = Bs[(c + gid) * AP + kk + tg + 4];
                } else {
                    bf[0] = Bs[(kk + tg    ) * BNP + c + gid];
                    bf[1] = Bs[(kk + tg + 4) * BNP + c + gid];
                }
                mma_m16n8k8(acc[0][ni], af[0], bf);
                mma_m16n8k8(acc[1][ni], af[1], bf);
            }
        }
        __syncthreads();
    }

    // ---- epilogue: alpha + bias, float2 stores ----
#pragma unroll
    for (int mi = 0; mi < 2; mi++) {
#pragma unroll
        for (int ni = 0; ni < 8; ni++) {
            const int r = wr + mi * 16 + gid;
            const int c = wc + ni * 8 + tg * 2;
            float b0 = bias ? bias[bn + c]     : 0.f;
            float b1 = bias ? bias[bn + c + 1] : 0.f;
            float2 v0 = make_float2(acc[mi][ni][0] * alpha + b0, acc[mi][ni][1] * alpha + b1);
            float2 v1 = make_float2(acc[mi][ni][2] * alpha + b0, acc[mi][ni][3] * alpha + b1);
            *reinterpret_cast<float2*>(Cg + (long long)r * N + c)       = v0;
            *reinterpret_cast<float2*>(Cg + (long long)(r + 8) * N + c) = v1;
        }
    }
}

// In-place softmax over rows of length 2048. One CTA (256 thr) per row;
// row held in registers: single global load + single store.
__global__ __launch_bounds__(256) void softmax2048(float* __restrict__ P) {
    constexpr int S = 2048;
    float* p = P + (long long)blockIdx.x * S;
    const int tid = threadIdx.x;

    float v[8];
    float mx = -3.4e38f;
#pragma unroll
    for (int j = 0; j < 8; j++) { v[j] = p[tid + j * 256]; mx = fmaxf(mx, v[j]); }
#pragma unroll
    for (int o = 16; o; o >>= 1) mx = fmaxf(mx, __shfl_xor_sync(0xffffffffu, mx, o));

    __shared__ float redm[8], reds[8];
    if ((tid & 31) == 0) redm[tid >> 5] = mx;
    __syncthreads();
    mx = redm[0];
#pragma unroll
    for (int j = 1; j < 8; j++) mx = fmaxf(mx, redm[j]);

    float s = 0.f;
#pragma unroll
    for (int j = 0; j < 8; j++) { v[j] = __expf(v[j] - mx); s += v[j]; }
#pragma unroll
    for (int o = 16; o; o >>= 1) s += __shfl_xor_sync(0xffffffffu, s, o);
    if ((tid & 31) == 0) reds[tid >> 5] = s;
    __syncthreads();
    s = reds[0];
#pragma unroll
    for (int j = 1; j < 8; j++) s += reds[j];

    const float inv = 1.0f / s;
#pragma unroll
    for (int j = 0; j < 8; j++) p[tid + j * 256] = v[j] * inv;
}

extern "C" void kernel_launch(void* const* d_in, const int* in_sizes, int n_in,
                              void* d_out, int out_size)
{
    const float* query  = (const float*)d_in[0];
    const float* key_in = (const float*)d_in[1];
    const float* value  = (const float*)d_in[2];
    const float* Wq     = (const float*)d_in[3];
    const float* bq     = (const float*)d_in[4];
    const float* Wk     = (const float*)d_in[5];
    const float* bk     = (const float*)d_in[6];
    // d_in[7] (Wv), d_in[8] (bv): unused by the reference math.
    float* out = (float*)d_out;

    float *Q, *Kb, *P;
    cudaGetSymbolAddress((void**)&Q,  g_Q);
    cudaGetSymbolAddress((void**)&Kb, g_K);
    cudaGetSymbolAddress((void**)&P,  g_P);

    constexpr int B = 4, S = 2048, D = 1024;
    const long long SD = (long long)S * D;
    const long long SS = (long long)S * S;
    const float scale = 0.03125f;  // 1/sqrt(1024)

    // Q = query @ Wq^T + bq ; K = key_in @ Wk^T + bk
    gemm_tf32<true><<<dim3(D / 128, S / 128, B), 256>>>(query,  Wq, Q,  S, D, D, SD, 0, SD, bq, 1.f);
    gemm_tf32<true><<<dim3(D / 128, S / 128, B), 256>>>(key_in, Wk, Kb, S, D, D, SD, 0, SD, bk, 1.f);
    // P = (Q @ K^T) * scale
    gemm_tf32<true><<<dim3(S / 128, S / 128, B), 256>>>(Q, Kb, P, S, S, D, SD, SD, SS, nullptr, scale);
    // softmax rows in place
    softmax2048<<<B * S, 256>>>(P);
    // out = P @ value   (NN)
    gemm_tf32<false><<<dim3(D / 128, S / 128, B), 256>>>(P, value, out, S, D, S, SS, SD, SD, nullptr, 1.f);
}

// round 8
// speedup vs baseline: 1.0025x; 1.0001x over previous
#include <cuda_runtime.h>
#include <cstdint>

// ---------------------------------------------------------------------------
// SingleAttention: out = softmax((query Wq^T + bq)(key Wk^T + bk)^T / 32) value
// B=4, S=2048, D=1024.  TF32 mma.sync GEMMs, fp32 accumulate + fp32 softmax.
// ---------------------------------------------------------------------------

// Scratch (static device globals: allocation-guard safe)
__device__ float g_Q[4ll * 2048 * 1024];
__device__ float g_K[4ll * 2048 * 1024];
__device__ float g_P[4ll * 2048 * 2048];

__device__ __forceinline__ uint32_t f2tf32(float x) {
    uint32_t r;
    asm("cvt.rna.tf32.f32 %0, %1;" : "=r"(r) : "f"(x));
    return r;
}

__device__ __forceinline__ void mma_m16n8k8(float c[4], const uint32_t a[4], const uint32_t b[2]) {
    asm volatile(
        "mma.sync.aligned.m16n8k8.row.col.f32.tf32.tf32.f32 "
        "{%0,%1,%2,%3}, {%4,%5,%6,%7}, {%8,%9}, {%0,%1,%2,%3};\n"
        : "+f"(c[0]), "+f"(c[1]), "+f"(c[2]), "+f"(c[3])
        : "r"(a[0]), "r"(a[1]), "r"(a[2]), "r"(a[3]), "r"(b[0]), "r"(b[1]));
}

// C[M,N] = alpha * A[M,K] * op(B) + bias
//   TRANSB=true : B is [N,K] row-major (C = A * B^T)
//   TRANSB=false: B is [K,N] row-major (C = A * B)
// All of M, N divisible by 128; K divisible by 32. lda=K, ldc=N.
template <bool TRANSB>
__global__ __launch_bounds__(256) void gemm_tf32(
    const float* __restrict__ A, const float* __restrict__ B, float* __restrict__ C,
    int M, int N, int K,
    long long aBatch, long long bBatch, long long cBatch,
    const float* __restrict__ bias, float alpha)
{
    constexpr int BM = 128, BN = 128, BK = 32;
    constexpr int AP  = 40;   // padded row stride (floats) for As / BsT: conflict-free frag loads
    constexpr int BNP = 136;  // padded row stride for BsN (NN path)

    __shared__ __align__(16) uint32_t As[BM * AP];
    __shared__ __align__(16) uint32_t Bs[BM * AP];  // NN path uses [BK][BNP] = 4352 <= 5120

    const int tid  = threadIdx.x;
    const int warp = tid >> 5, lane = tid & 31;
    const int gid  = lane >> 2, tg = lane & 3;
    const int wr   = (warp & 3) * 32;   // warp row in block tile
    const int wc   = (warp >> 2) * 64;  // warp col in block tile

    const int bm = blockIdx.y * BM;
    const int bn = blockIdx.x * BN;
    const int bz = blockIdx.z;

    const float* Ag = A + (long long)bz * aBatch + (long long)bm * K;
    const float* Bg = B + (long long)bz * bBatch;
    float*       Cg = C + (long long)bz * cBatch + (long long)bm * N + bn;

    float acc[2][8][4];
#pragma unroll
    for (int i = 0; i < 2; i++)
#pragma unroll
        for (int j = 0; j < 8; j++)
#pragma unroll
            for (int q = 0; q < 4; q++) acc[i][j][q] = 0.f;

    for (int kt = 0; kt < K; kt += BK) {
        // ---- load A tile 128x32 (float4) ----
#pragma unroll
        for (int it = 0; it < 4; it++) {
            int i = tid + it * 256;
            int r = i >> 3, c = (i & 7) << 2;
            float4 v = *reinterpret_cast<const float4*>(Ag + (long long)r * K + kt + c);
            uint32_t* dst = &As[r * AP + c];
            dst[0] = f2tf32(v.x); dst[1] = f2tf32(v.y);
            dst[2] = f2tf32(v.z); dst[3] = f2tf32(v.w);
        }
        // ---- load B tile ----
        if (TRANSB) {
#pragma unroll
            for (int it = 0; it < 4; it++) {
                int i = tid + it * 256;
                int r = i >> 3, c = (i & 7) << 2;
                float4 v = *reinterpret_cast<const float4*>(Bg + (long long)(bn + r) * K + kt + c);
                uint32_t* dst = &Bs[r * AP + c];
                dst[0] = f2tf32(v.x); dst[1] = f2tf32(v.y);
                dst[2] = f2tf32(v.z); dst[3] = f2tf32(v.w);
            }
        } else {
#pragma unroll
            for (int it = 0; it < 4; it++) {
                int i = tid + it * 256;
                int k = i >> 5, n = (i & 31) << 2;
                float4 v = *reinterpret_cast<const float4*>(Bg + (long long)(kt + k) * N + bn + n);
                uint32_t* dst = &Bs[k * BNP + n];
                dst[0] = f2tf32(v.x); dst[1] = f2tf32(v.y);
                dst[2] = f2tf32(v.z); dst[3] = f2tf32(v.w);
            }
        }
        __syncthreads();

        // ---- compute: 4 k-steps of 8 ----
#pragma unroll
        for (int ks = 0; ks < 4; ks++) {
            const int kk = ks * 8;
            uint32_t af[2][4];
#pragma unroll
            for (int mi = 0; mi < 2; mi++) {
                const int r = wr + mi * 16;
                af[mi][0] = As[(r + gid    ) * AP + kk + tg    ];
                af[mi][1] = As[(r + gid + 8) * AP + kk + tg    ];
                af[mi][2] = As[(r + gid    ) * AP + kk + tg + 4];
                af[mi][3] = As[(r + gid + 8) * AP + kk + tg + 4];
            }
#pragma unroll
            for (int ni = 0; ni < 8; ni++) {
                const int c = wc + ni * 8;
                uint32_t bf[2];
                if (TRANSB) {
                    bf[0] = Bs[(c + gid) * AP + kk + tg    ];
                    bf[1] = Bs[(c + gid) * AP + kk + tg + 4];
                } else {
                    bf[0] = Bs[(kk + tg    ) * BNP + c + gid];
                    bf[1] = Bs[(kk + tg + 4) * BNP + c + gid];
                }
                mma_m16n8k8(acc[0][ni], af[0], bf);
                mma_m16n8k8(acc[1][ni], af[1], bf);
            }
        }
        __syncthreads();
    }

    // ---- epilogue: alpha + bias, float2 stores ----
#pragma unroll
    for (int mi = 0; mi < 2; mi++) {
#pragma unroll
        for (int ni = 0; ni < 8; ni++) {
            const int r = wr + mi * 16 + gid;
            const int c = wc + ni * 8 + tg * 2;
            float b0 = bias ? bias[bn + c]     : 0.f;
            float b1 = bias ? bias[bn + c + 1] : 0.f;
            float2 v0 = make_float2(acc[mi][ni][0] * alpha + b0, acc[mi][ni][1] * alpha + b1);
            float2 v1 = make_float2(acc[mi][ni][2] * alpha + b0, acc[mi][ni][3] * alpha + b1);
            *reinterpret_cast<float2*>(Cg + (long long)r * N + c)       = v0;
            *reinterpret_cast<float2*>(Cg + (long long)(r + 8) * N + c) = v1;
        }
    }
}

// In-place softmax over rows of length 2048. One CTA (256 thr) per row;
// row held in registers: single global load + single store.
__global__ __launch_bounds__(256) void softmax2048(float* __restrict__ P) {
    constexpr int S = 2048;
    float* p = P + (long long)blockIdx.x * S;
    const int tid = threadIdx.x;

    float v[8];
    float mx = -3.4e38f;
#pragma unroll
    for (int j = 0; j < 8; j++) { v[j] = p[tid + j * 256]; mx = fmaxf(mx, v[j]); }
#pragma unroll
    for (int o = 16; o; o >>= 1) mx = fmaxf(mx, __shfl_xor_sync(0xffffffffu, mx, o));

    __shared__ float redm[8], reds[8];
    if ((tid & 31) == 0) redm[tid >> 5] = mx;
    __syncthreads();
    mx = redm[0];
#pragma unroll
    for (int j = 1; j < 8; j++) mx = fmaxf(mx, redm[j]);

    float s = 0.f;
#pragma unroll
    for (int j = 0; j < 8; j++) { v[j] = __expf(v[j] - mx); s += v[j]; }
#pragma unroll
    for (int o = 16; o; o >>= 1) s += __shfl_xor_sync(0xffffffffu, s, o);
    if ((tid & 31) == 0) reds[tid >> 5] = s;
    __syncthreads();
    s = reds[0];
#pragma unroll
    for (int j = 1; j < 8; j++) s += reds[j];

    const float inv = 1.0f / s;
#pragma unroll
    for (int j = 0; j < 8; j++) p[tid + j * 256] = v[j] * inv;
}

extern "C" void kernel_launch(void* const* d_in, const int* in_sizes, int n_in,
                              void* d_out, int out_size)
{
    const float* query  = (const float*)d_in[0];
    const float* key_in = (const float*)d_in[1];
    const float* value  = (const float*)d_in[2];
    const float* Wq     = (const float*)d_in[3];
    const float* bq     = (const float*)d_in[4];
    const float* Wk     = (const float*)d_in[5];
    const float* bk     = (const float*)d_in[6];
    // d_in[7] (Wv), d_in[8] (bv): unused by the reference math.
    float* out = (float*)d_out;

    float *Q, *Kb, *P;
    cudaGetSymbolAddress((void**)&Q,  g_Q);
    cudaGetSymbolAddress((void**)&Kb, g_K);
    cudaGetSymbolAddress((void**)&P,  g_P);

    constexpr int B = 4, S = 2048, D = 1024;
    const long long SD = (long long)S * D;
    const long long SS = (long long)S * S;
    const float scale = 0.03125f;  // 1/sqrt(1024)

    // Q = query @ Wq^T + bq ; K = key_in @ Wk^T + bk
    gemm_tf32<true><<<dim3(D / 128, S / 128, B), 256>>>(query,  Wq, Q,  S, D, D, SD, 0, SD, bq, 1.f);
    gemm_tf32<true><<<dim3(D / 128, S / 128, B), 256>>>(key_in, Wk, Kb, S, D, D, SD, 0, SD, bk, 1.f);
    // P = (Q @ K^T) * scale
    gemm_tf32<true><<<dim3(S / 128, S / 128, B), 256>>>(Q, Kb, P, S, S, D, SD, SD, SS, nullptr, scale);
    // softmax rows in place
    softmax2048<<<B * S, 256>>>(P);
    // out = P @ value   (NN)
    gemm_tf32<false><<<dim3(D / 128, S / 128, B), 256>>>(P, value, out, S, D, S, SS, SD, SD, nullptr, 1.f);
}

// round 9
// speedup vs baseline: 1.0037x; 1.0011x over previous
#include <cuda_runtime.h>
#include <cstdint>

// ---------------------------------------------------------------------------
// SingleAttention: out = softmax((query Wq^T + bq)(key Wk^T + bk)^T / 32) value
// B=4, S=2048, D=1024.  TF32 mma.sync GEMMs, fp32 accumulate + fp32 softmax.
// ---------------------------------------------------------------------------

// Scratch (static device globals: allocation-guard safe)
__device__ float g_Q[4ll * 2048 * 1024];
__device__ float g_K[4ll * 2048 * 1024];
__device__ float g_P[4ll * 2048 * 2048];

__device__ __forceinline__ uint32_t f2tf32(float x) {
    uint32_t r;
    asm("cvt.rna.tf32.f32 %0, %1;" : "=r"(r) : "f"(x));
    return r;
}

__device__ __forceinline__ void mma_m16n8k8(float c[4], const uint32_t a[4], const uint32_t b[2]) {
    asm volatile(
        "mma.sync.aligned.m16n8k8.row.col.f32.tf32.tf32.f32 "
        "{%0,%1,%2,%3}, {%4,%5,%6,%7}, {%8,%9}, {%0,%1,%2,%3};\n"
        : "+f"(c[0]), "+f"(c[1]), "+f"(c[2]), "+f"(c[3])
        : "r"(a[0]), "r"(a[1]), "r"(a[2]), "r"(a[3]), "r"(b[0]), "r"(b[1]));
}

// C[M,N] = alpha * A[M,K] * op(B) + bias
//   TRANSB=true : B is [N,K] row-major (C = A * B^T)
//   TRANSB=false: B is [K,N] row-major (C = A * B)
// All of M, N divisible by 128; K divisible by 32. lda=K, ldc=N.
template <bool TRANSB>
__global__ __launch_bounds__(256) void gemm_tf32(
    const float* __restrict__ A, const float* __restrict__ B, float* __restrict__ C,
    int M, int N, int K,
    long long aBatch, long long bBatch, long long cBatch,
    const float* __restrict__ bias, float alpha)
{
    constexpr int BM = 128, BN = 128, BK = 32;
    constexpr int AP  = 40;   // padded row stride (floats) for As / BsT: conflict-free frag loads
    constexpr int BNP = 136;  // padded row stride for BsN (NN path)

    __shared__ __align__(16) uint32_t As[BM * AP];
    __shared__ __align__(16) uint32_t Bs[BM * AP];  // NN path uses [BK][BNP] = 4352 <= 5120

    const int tid  = threadIdx.x;
    const int warp = tid >> 5, lane = tid & 31;
    const int gid  = lane >> 2, tg = lane & 3;
    const int wr   = (warp & 3) * 32;   // warp row in block tile
    const int wc   = (warp >> 2) * 64;  // warp col in block tile

    const int bm = blockIdx.y * BM;
    const int bn = blockIdx.x * BN;
    const int bz = blockIdx.z;

    const float* Ag = A + (long long)bz * aBatch + (long long)bm * K;
    const float* Bg = B + (long long)bz * bBatch;
    float*       Cg = C + (long long)bz * cBatch + (long long)bm * N + bn;

    float acc[2][8][4];
#pragma unroll
    for (int i = 0; i < 2; i++)
#pragma unroll
        for (int j = 0; j < 8; j++)
#pragma unroll
            for (int q = 0; q < 4; q++) acc[i][j][q] = 0.f;

    for (int kt = 0; kt < K; kt += BK) {
        // ---- load A tile 128x32 (float4) ----
#pragma unroll
        for (int it = 0; it < 4; it++) {
            int i = tid + it * 256;
            int r = i >> 3, c = (i & 7) << 2;
            float4 v = *reinterpret_cast<const float4*>(Ag + (long long)r * K + kt + c);
            uint32_t* dst = &As[r * AP + c];
            dst[0] = f2tf32(v.x); dst[1] = f2tf32(v.y);
            dst[2] = f2tf32(v.z); dst[3] = f2tf32(v.w);
        }
        // ---- load B tile ----
        if (TRANSB) {
#pragma unroll
            for (int it = 0; it < 4; it++) {
                int i = tid + it * 256;
                int r = i >> 3, c = (i & 7) << 2;
                float4 v = *reinterpret_cast<const float4*>(Bg + (long long)(bn + r) * K + kt + c);
                uint32_t* dst = &Bs[r * AP + c];
                dst[0] = f2tf32(v.x); dst[1] = f2tf32(v.y);
                dst[2] = f2tf32(v.z); dst[3] = f2tf32(v.w);
            }
        } else {
#pragma unroll
            for (int it = 0; it < 4; it++) {
                int i = tid + it * 256;
                int k = i >> 5, n = (i & 31) << 2;
                float4 v = *reinterpret_cast<const float4*>(Bg + (long long)(kt + k) * N + bn + n);
                uint32_t* dst = &Bs[k * BNP + n];
                dst[0] = f2tf32(v.x); dst[1] = f2tf32(v.y);
                dst[2] = f2tf32(v.z); dst[3] = f2tf32(v.w);
            }
        }
        __syncthreads();

        // ---- compute: 4 k-steps of 8 ----
#pragma unroll
        for (int ks = 0; ks < 4; ks++) {
            const int kk = ks * 8;
            uint32_t af[2][4];
#pragma unroll
            for (int mi = 0; mi < 2; mi++) {
                const int r = wr + mi * 16;
                af[mi][0] = As[(r + gid    ) * AP + kk + tg    ];
                af[mi][1] = As[(r + gid + 8) * AP + kk + tg    ];
                af[mi][2] = As[(r + gid    ) * AP + kk + tg + 4];
                af[mi][3] = As[(r + gid + 8) * AP + kk + tg + 4];
            }
#pragma unroll
            for (int ni = 0; ni < 8; ni++) {
                const int c = wc + ni * 8;
                uint32_t bf[2];
                if (TRANSB) {
                    bf[0] = Bs[(c + gid) * AP + kk + tg    ];
                    bf[1] = Bs[(c + gid) * AP + kk + tg + 4];
                } else {
                    bf[0] = Bs[(kk + tg    ) * BNP + c + gid];
                    bf[1] = Bs[(kk + tg + 4) * BNP + c + gid];
                }
                mma_m16n8k8(acc[0][ni], af[0], bf);
                mma_m16n8k8(acc[1][ni], af[1], bf);
            }
        }
        __syncthreads();
    }

    // ---- epilogue: alpha + bias, float2 stores ----
#pragma unroll
    for (int mi = 0; mi < 2; mi++) {
#pragma unroll
        for (int ni = 0; ni < 8; ni++) {
            const int r = wr + mi * 16 + gid;
            const int c = wc + ni * 8 + tg * 2;
            float b0 = bias ? bias[bn + c]     : 0.f;
            float b1 = bias ? bias[bn + c + 1] : 0.f;
            float2 v0 = make_float2(acc[mi][ni][0] * alpha + b0, acc[mi][ni][1] * alpha + b1);
            float2 v1 = make_float2(acc[mi][ni][2] * alpha + b0, acc[mi][ni][3] * alpha + b1);
            *reinterpret_cast<float2*>(Cg + (long long)r * N + c)       = v0;
            *reinterpret_cast<float2*>(Cg + (long long)(r + 8) * N + c) = v1;
        }
    }
}

// In-place softmax over rows of length 2048. One CTA (256 thr) per row;
// row held in registers: single global load + single store.
__global__ __launch_bounds__(256) void softmax2048(float* __restrict__ P) {
    constexpr int S = 2048;
    float* p = P + (long long)blockIdx.x * S;
    const int tid = threadIdx.x;

    float v[8];
    float mx = -3.4e38f;
#pragma unroll
    for (int j = 0; j < 8; j++) { v[j] = p[tid + j * 256]; mx = fmaxf(mx, v[j]); }
#pragma unroll
    for (int o = 16; o; o >>= 1) mx = fmaxf(mx, __shfl_xor_sync(0xffffffffu, mx, o));

    __shared__ float redm[8], reds[8];
    if ((tid & 31) == 0) redm[tid >> 5] = mx;
    __syncthreads();
    mx = redm[0];
#pragma unroll
    for (int j = 1; j < 8; j++) mx = fmaxf(mx, redm[j]);

    float s = 0.f;
#pragma unroll
    for (int j = 0; j < 8; j++) { v[j] = __expf(v[j] - mx); s += v[j]; }
#pragma unroll
    for (int o = 16; o; o >>= 1) s += __shfl_xor_sync(0xffffffffu, s, o);
    if ((tid & 31) == 0) reds[tid >> 5] = s;
    __syncthreads();
    s = reds[0];
#pragma unroll
    for (int j = 1; j < 8; j++) s += reds[j];

    const float inv = 1.0f / s;
#pragma unroll
    for (int j = 0; j < 8; j++) p[tid + j * 256] = v[j] * inv;
}

extern "C" void kernel_launch(void* const* d_in, const int* in_sizes, int n_in,
                              void* d_out, int out_size)
{
    const float* query  = (const float*)d_in[0];
    const float* key_in = (const float*)d_in[1];
    const float* value  = (const float*)d_in[2];
    const float* Wq     = (const float*)d_in[3];
    const float* bq     = (const float*)d_in[4];
    const float* Wk     = (const float*)d_in[5];
    const float* bk     = (const float*)d_in[6];
    // d_in[7] (Wv), d_in[8] (bv): unused by the reference math.
    float* out = (float*)d_out;

    float *Q, *Kb, *P;
    cudaGetSymbolAddress((void**)&Q,  g_Q);
    cudaGetSymbolAddress((void**)&Kb, g_K);
    cudaGetSymbolAddress((void**)&P,  g_P);

    constexpr int B = 4, S = 2048, D = 1024;
    const long long SD = (long long)S * D;
    const long long SS = (long long)S * S;
    const float scale = 0.03125f;  // 1/sqrt(1024)

    // Q = query @ Wq^T + bq ; K = key_in @ Wk^T + bk
    gemm_tf32<true><<<dim3(D / 128, S / 128, B), 256>>>(query,  Wq, Q,  S, D, D, SD, 0, SD, bq, 1.f);
    gemm_tf32<true><<<dim3(D / 128, S / 128, B), 256>>>(key_in, Wk, Kb, S, D, D, SD, 0, SD, bk, 1.f);
    // P = (Q @ K^T) * scale
    gemm_tf32<true><<<dim3(S / 128, S / 128, B), 256>>>(Q, Kb, P, S, S, D, SD, SD, SS, nullptr, scale);
    // softmax rows in place
    softmax2048<<<B * S, 256>>>(P);
    // out = P @ value   (NN)
    gemm_tf32<false><<<dim3(D / 128, S / 128, B), 256>>>(P, value, out, S, D, S, SS, SD, SD, nullptr, 1.f);
}